// round 1
// baseline (speedup 1.0000x reference)
#include <cuda_runtime.h>
#include <cstdint>

#define N_NODES 50000
#define N_EDGES 1600000
#define D_IN    128
#define D_EDGE  64
#define D_NODE  128
#define D_SUM   (D_IN + D_EDGE)   // 192

// Scratch (allocation-free rule: __device__ globals)
__device__ float g_proj[(size_t)N_NODES * D_EDGE];  // relu(X@W_fs + b_fs), 12.8 MB
__device__ float g_agg [(size_t)N_NODES * D_EDGE];  // segment_max result,  12.8 MB

typedef unsigned long long ull;

__device__ __forceinline__ ull pack2(float lo, float hi) {
    ull r;
    asm("mov.b64 %0, {%1, %2};" : "=l"(r) : "f"(lo), "f"(hi));
    return r;
}
__device__ __forceinline__ void unpack2(ull v, float& lo, float& hi) {
    asm("mov.b64 {%0, %1}, %2;" : "=f"(lo), "=f"(hi) : "l"(v));
}
// Packed fp32x2 FMA (sm_103a FFMA2): 2 fp32 FMAs per instruction.
__device__ __forceinline__ ull fma2(ull a, ull b, ull c) {
    ull d;
    asm("fma.rn.f32x2 %0, %1, %2, %3;" : "=l"(d) : "l"(a), "l"(b), "l"(c));
    return d;
}

// ---------------------------------------------------------------------------
// Zero the aggregation buffer (0.0f bits == 0, required for int-atomicMax trick)
// ---------------------------------------------------------------------------
__global__ void k_zero() {
    int i = blockIdx.x * 256 + threadIdx.x;
    if (i < N_NODES * D_EDGE / 4)
        ((float4*)g_agg)[i] = make_float4(0.f, 0.f, 0.f, 0.f);
}

// ---------------------------------------------------------------------------
// Kernel A: g_proj = relu(X @ W_fs + b_fs)   [50000,128]@[128,64]
// Block 256 (8 warps), warp computes 4 rows x 64 cols (2 cols/lane).
// W pair-interleaved in smem: Wp[(k/2)*128 + j*2 + (k&1)] -> LDS.64 per K-pair.
// ---------------------------------------------------------------------------
__global__ __launch_bounds__(256) void k_proj(const float* __restrict__ X,
                                              const float* __restrict__ W,
                                              const float* __restrict__ b) {
    extern __shared__ float sm[];
    float* Wp = sm;                         // 128*64 floats (32 KB)
    float* Xs = sm + D_IN * D_EDGE;         // 8*4*128 floats (16 KB)
    const int tid = threadIdx.x;

    for (int i = tid; i < D_IN * D_EDGE; i += 256) {
        int k = i >> 6, j = i & 63;
        Wp[(k >> 1) * 128 + j * 2 + (k & 1)] = W[i];
    }
    __syncthreads();

    const int warp = tid >> 5, lane = tid & 31;
    float* xrow0 = Xs + warp * 4 * D_IN;
    const float bj0 = __ldg(&b[lane]);
    const float bj1 = __ldg(&b[lane + 32]);
    const int nTiles = (N_NODES + 31) >> 5;

    for (int tile = blockIdx.x; tile < nTiles; tile += gridDim.x) {
        const int rowBase = tile * 32 + warp * 4;
        #pragma unroll
        for (int i = 0; i < 4; i++) {
            int r = rowBase + i;
            float4 v = make_float4(0.f, 0.f, 0.f, 0.f);
            if (r < N_NODES)
                v = __ldg((const float4*)(X + (size_t)r * D_IN) + lane);
            ((float4*)(xrow0 + i * D_IN))[lane] = v;
        }
        __syncwarp();

        ull acc[4][2];
        #pragma unroll
        for (int i = 0; i < 4; i++) { acc[i][0] = 0ull; acc[i][1] = 0ull; }

        for (int kk = 0; kk < D_IN; kk += 4) {
            const float* wb = Wp + (kk >> 1) * 128;
            ull w0a = *(const ull*)(wb + lane * 2);
            ull w1a = *(const ull*)(wb + (lane + 32) * 2);
            ull w0b = *(const ull*)(wb + 128 + lane * 2);
            ull w1b = *(const ull*)(wb + 128 + (lane + 32) * 2);
            #pragma unroll
            for (int i = 0; i < 4; i++) {
                float4 xv = *(const float4*)(xrow0 + i * D_IN + kk);
                ull xa = pack2(xv.x, xv.y);
                ull xb = pack2(xv.z, xv.w);
                acc[i][0] = fma2(xa, w0a, acc[i][0]);
                acc[i][1] = fma2(xa, w1a, acc[i][1]);
                acc[i][0] = fma2(xb, w0b, acc[i][0]);
                acc[i][1] = fma2(xb, w1b, acc[i][1]);
            }
        }

        #pragma unroll
        for (int i = 0; i < 4; i++) {
            int r = rowBase + i;
            if (r < N_NODES) {
                float l0, h0, l1, h1;
                unpack2(acc[i][0], l0, h0);
                unpack2(acc[i][1], l1, h1);
                g_proj[(size_t)r * D_EDGE + lane]      = fmaxf(l0 + h0 + bj0, 0.f);
                g_proj[(size_t)r * D_EDGE + lane + 32] = fmaxf(l1 + h1 + bj1, 0.f);
            }
        }
        __syncwarp();
    }
}

// ---------------------------------------------------------------------------
// Kernel B: scatter-max.  16 threads per edge, float4 gather of g_proj[sender],
// int-atomicMax (valid: all values >= 0 after relu; agg zero-initialized).
// ---------------------------------------------------------------------------
__global__ __launch_bounds__(256) void k_edge(const int* __restrict__ senders,
                                              const int* __restrict__ receivers) {
    int gid = blockIdx.x * 256 + threadIdx.x;
    int e = gid >> 4;
    if (e >= N_EDGES) return;
    int q = gid & 15;
    int s = __ldg(&senders[e]);
    int r = __ldg(&receivers[e]);
    float4 v = __ldg((const float4*)g_proj + s * 16 + q);
    int* dst = (int*)g_agg + (size_t)r * D_EDGE + q * 4;
    atomicMax(dst + 0, __float_as_int(v.x));
    atomicMax(dst + 1, __float_as_int(v.y));
    atomicMax(dst + 2, __float_as_int(v.z));
    atomicMax(dst + 3, __float_as_int(v.w));
}

// ---------------------------------------------------------------------------
// Kernel C: out = X@W_gn + agg@W_gin + (b_gn + b_gin)
// Fused as [X | agg] (192) @ [W_gn ; W_gin] (192x128).
// Block 256 (8 warps), warp = 4 rows x 128 cols (4 cols/lane).
// Weight panel (96 KB, pair-interleaved) loaded once per block; grid-strided tiles.
// ---------------------------------------------------------------------------
__global__ __launch_bounds__(256) void k_final(const float* __restrict__ X,
                                               const float* __restrict__ Wgn,
                                               const float* __restrict__ bgn,
                                               const float* __restrict__ Wgin,
                                               const float* __restrict__ bgin,
                                               float* __restrict__ out) {
    extern __shared__ float sm[];
    float* Wp   = sm;                        // 192*128 floats (96 KB), pair-interleaved
    float* Xs   = Wp + D_SUM * D_NODE;       // 8*4*192 floats (24 KB)
    float* bias = Xs + 8 * 4 * D_SUM;        // 128 floats
    const int tid = threadIdx.x;

    for (int i = tid; i < D_SUM * D_NODE; i += 256) {
        int k = i >> 7, j = i & 127;
        float v = (k < D_IN) ? Wgn[i] : Wgin[i - D_IN * D_NODE];
        Wp[(k >> 1) * 256 + j * 2 + (k & 1)] = v;
    }
    if (tid < D_NODE) bias[tid] = bgn[tid] + bgin[tid];
    __syncthreads();

    const int warp = tid >> 5, lane = tid & 31;
    float* xrow0 = Xs + warp * 4 * D_SUM;
    const int nTiles = (N_NODES + 31) >> 5;

    for (int tile = blockIdx.x; tile < nTiles; tile += gridDim.x) {
        const int rowBase = tile * 32 + warp * 4;
        #pragma unroll
        for (int i = 0; i < 4; i++) {
            int r = rowBase + i;
            float* xr = xrow0 + i * D_SUM;
            if (r < N_NODES) {
                ((float4*)xr)[lane] = __ldg((const float4*)(X + (size_t)r * D_IN) + lane);
                if (lane < 16)
                    ((float4*)(xr + D_IN))[lane] =
                        *((const float4*)(g_agg + (size_t)r * D_EDGE) + lane);
            } else {
                ((float4*)xr)[lane] = make_float4(0.f, 0.f, 0.f, 0.f);
                if (lane < 16)
                    ((float4*)(xr + D_IN))[lane] = make_float4(0.f, 0.f, 0.f, 0.f);
            }
        }
        __syncwarp();

        ull acc[4][4];
        #pragma unroll
        for (int i = 0; i < 4; i++)
            #pragma unroll
            for (int c = 0; c < 4; c++) acc[i][c] = 0ull;

        for (int kk = 0; kk < D_SUM; kk += 4) {
            const float* wb = Wp + (kk >> 1) * 256;
            ull wA[4], wB[4];
            #pragma unroll
            for (int c = 0; c < 4; c++) {
                wA[c] = *(const ull*)(wb + (lane + c * 32) * 2);
                wB[c] = *(const ull*)(wb + 256 + (lane + c * 32) * 2);
            }
            #pragma unroll
            for (int i = 0; i < 4; i++) {
                float4 xv = *(const float4*)(xrow0 + i * D_SUM + kk);
                ull xa = pack2(xv.x, xv.y);
                ull xb = pack2(xv.z, xv.w);
                #pragma unroll
                for (int c = 0; c < 4; c++) {
                    acc[i][c] = fma2(xa, wA[c], acc[i][c]);
                    acc[i][c] = fma2(xb, wB[c], acc[i][c]);
                }
            }
        }

        #pragma unroll
        for (int i = 0; i < 4; i++) {
            int r = rowBase + i;
            if (r < N_NODES) {
                #pragma unroll
                for (int c = 0; c < 4; c++) {
                    float lo, hi;
                    unpack2(acc[i][c], lo, hi);
                    out[(size_t)r * D_NODE + lane + c * 32] = lo + hi + bias[lane + c * 32];
                }
            }
        }
        __syncwarp();
    }
}

// ---------------------------------------------------------------------------
extern "C" void kernel_launch(void* const* d_in, const int* in_sizes, int n_in,
                              void* d_out, int out_size) {
    const float* X       = (const float*)d_in[0];
    const float* W_fs    = (const float*)d_in[1];
    const float* b_fs    = (const float*)d_in[2];
    const float* W_gn    = (const float*)d_in[3];
    const float* b_gn    = (const float*)d_in[4];
    const float* W_gin   = (const float*)d_in[5];
    const float* b_gin   = (const float*)d_in[6];
    const int* senders   = (const int*)d_in[7];
    const int* receivers = (const int*)d_in[8];
    float* out = (float*)d_out;

    const int SMEM_A = (D_IN * D_EDGE + 8 * 4 * D_IN) * 4;                    // 49152
    const int SMEM_C = (D_SUM * D_NODE + 8 * 4 * D_SUM + D_NODE) * 4;        // 123392

    cudaFuncSetAttribute(k_proj,  cudaFuncAttributeMaxDynamicSharedMemorySize, SMEM_A);
    cudaFuncSetAttribute(k_final, cudaFuncAttributeMaxDynamicSharedMemorySize, SMEM_C);

    k_zero<<<(N_NODES * D_EDGE / 4 + 255) / 256, 256>>>();
    k_proj<<<592, 256, SMEM_A>>>(X, W_fs, b_fs);
    k_edge<<<(N_EDGES * 16 + 255) / 256, 256>>>(senders, receivers);
    k_final<<<148, 256, SMEM_C>>>(X, W_gn, b_gn, W_gin, b_gin, out);
}

// round 2
// speedup vs baseline: 1.5107x; 1.5107x over previous
#include <cuda_runtime.h>
#include <cstdint>

#define N_NODES 50000
#define N_EDGES 1600000
#define D_IN    128
#define D_EDGE  64
#define D_NODE  128
#define D_SUM   (D_IN + D_EDGE)   // 192

// Scratch (allocation-free rule: __device__ globals)
__device__ float g_proj[(size_t)N_NODES * D_EDGE];  // relu(X@W_fs + b_fs), 12.8 MB
__device__ float g_agg [(size_t)N_NODES * D_EDGE];  // segment_max result,  12.8 MB

typedef unsigned long long ull;

__device__ __forceinline__ ull pack2(float lo, float hi) {
    ull r;
    asm("mov.b64 %0, {%1, %2};" : "=l"(r) : "f"(lo), "f"(hi));
    return r;
}
__device__ __forceinline__ void unpack2(ull v, float& lo, float& hi) {
    asm("mov.b64 {%0, %1}, %2;" : "=f"(lo), "=f"(hi) : "l"(v));
}
// Packed fp32x2 FMA (sm_103a FFMA2): 2 fp32 FMAs per instruction.
__device__ __forceinline__ ull fma2(ull a, ull b, ull c) {
    ull d;
    asm("fma.rn.f32x2 %0, %1, %2, %3;" : "=l"(d) : "l"(a), "l"(b), "l"(c));
    return d;
}

// ---------------------------------------------------------------------------
// Zero the aggregation buffer (0.0f bits == 0, required for int-atomicMax trick)
// ---------------------------------------------------------------------------
__global__ void k_zero() {
    int i = blockIdx.x * 256 + threadIdx.x;
    if (i < N_NODES * D_EDGE / 4)
        ((float4*)g_agg)[i] = make_float4(0.f, 0.f, 0.f, 0.f);
}

// ---------------------------------------------------------------------------
// Kernel A: g_proj = relu(X @ W_fs + b_fs)   [50000,128]@[128,64]
// Block 256 (8 warps), warp computes 4 rows x 64 cols (2 cols/lane).
// ---------------------------------------------------------------------------
__global__ __launch_bounds__(256) void k_proj(const float* __restrict__ X,
                                              const float* __restrict__ W,
                                              const float* __restrict__ b) {
    extern __shared__ float sm[];
    float* Wp = sm;                         // 128*64 floats (32 KB)
    float* Xs = sm + D_IN * D_EDGE;         // 8*4*128 floats (16 KB)
    const int tid = threadIdx.x;

    for (int i = tid; i < D_IN * D_EDGE; i += 256) {
        int k = i >> 6, j = i & 63;
        Wp[(k >> 1) * 128 + j * 2 + (k & 1)] = W[i];
    }
    __syncthreads();

    const int warp = tid >> 5, lane = tid & 31;
    float* xrow0 = Xs + warp * 4 * D_IN;
    const float bj0 = __ldg(&b[lane]);
    const float bj1 = __ldg(&b[lane + 32]);
    const int nTiles = (N_NODES + 31) >> 5;

    for (int tile = blockIdx.x; tile < nTiles; tile += gridDim.x) {
        const int rowBase = tile * 32 + warp * 4;
        #pragma unroll
        for (int i = 0; i < 4; i++) {
            int r = rowBase + i;
            float4 v = make_float4(0.f, 0.f, 0.f, 0.f);
            if (r < N_NODES)
                v = __ldg((const float4*)(X + (size_t)r * D_IN) + lane);
            ((float4*)(xrow0 + i * D_IN))[lane] = v;
        }
        __syncwarp();

        ull acc[4][2];
        #pragma unroll
        for (int i = 0; i < 4; i++) { acc[i][0] = 0ull; acc[i][1] = 0ull; }

        for (int kk = 0; kk < D_IN; kk += 4) {
            const float* wb = Wp + (kk >> 1) * 128;
            ull w0a = *(const ull*)(wb + lane * 2);
            ull w1a = *(const ull*)(wb + (lane + 32) * 2);
            ull w0b = *(const ull*)(wb + 128 + lane * 2);
            ull w1b = *(const ull*)(wb + 128 + (lane + 32) * 2);
            #pragma unroll
            for (int i = 0; i < 4; i++) {
                float4 xv = *(const float4*)(xrow0 + i * D_IN + kk);
                ull xa = pack2(xv.x, xv.y);
                ull xb = pack2(xv.z, xv.w);
                acc[i][0] = fma2(xa, w0a, acc[i][0]);
                acc[i][1] = fma2(xa, w1a, acc[i][1]);
                acc[i][0] = fma2(xb, w0b, acc[i][0]);
                acc[i][1] = fma2(xb, w1b, acc[i][1]);
            }
        }

        #pragma unroll
        for (int i = 0; i < 4; i++) {
            int r = rowBase + i;
            if (r < N_NODES) {
                float l0, h0, l1, h1;
                unpack2(acc[i][0], l0, h0);
                unpack2(acc[i][1], l1, h1);
                g_proj[(size_t)r * D_EDGE + lane]      = fmaxf(l0 + h0 + bj0, 0.f);
                g_proj[(size_t)r * D_EDGE + lane + 32] = fmaxf(l1 + h1 + bj1, 0.f);
            }
        }
        __syncwarp();
    }
}

// ---------------------------------------------------------------------------
// Kernel B: scatter-max with read-before-atomic filter.
// Safe: agg values are monotonically non-decreasing and any (possibly stale)
// read is <= the true current value, so skipping when v <= cur never loses
// a needed update. Cuts ~87% of the 102M L2 atomics (mean degree 32).
// ---------------------------------------------------------------------------
__global__ __launch_bounds__(256) void k_edge(const int* __restrict__ senders,
                                              const int* __restrict__ receivers) {
    int gid = blockIdx.x * 256 + threadIdx.x;
    int e = gid >> 4;
    if (e >= N_EDGES) return;
    int q = gid & 15;
    int s = __ldg(&senders[e]);
    int r = __ldg(&receivers[e]);
    float4 v = __ldg((const float4*)g_proj + s * 16 + q);
    float4 cur = *((const float4*)g_agg + (size_t)r * 16 + q);
    int* dst = (int*)g_agg + (size_t)r * D_EDGE + q * 4;
    if (v.x > cur.x) atomicMax(dst + 0, __float_as_int(v.x));
    if (v.y > cur.y) atomicMax(dst + 1, __float_as_int(v.y));
    if (v.z > cur.z) atomicMax(dst + 2, __float_as_int(v.z));
    if (v.w > cur.w) atomicMax(dst + 3, __float_as_int(v.w));
}

// ---------------------------------------------------------------------------
// Kernel C: out = X@W_gn + agg@W_gin + (b_gn + b_gin)
// Fused as [X | agg] (192) @ [W_gn ; W_gin] (192x128).
// Column-split: each block owns 64 of 128 output columns (48KB weight panel)
// -> 2 blocks/SM, 16 resident warps. Warp computes 8 rows x 64 cols
// (2 cols/lane), acc[8][2] for ILP. Tile = 64 rows.
// ---------------------------------------------------------------------------
__global__ __launch_bounds__(256) void k_final(const float* __restrict__ X,
                                               const float* __restrict__ Wgn,
                                               const float* __restrict__ bgn,
                                               const float* __restrict__ Wgin,
                                               const float* __restrict__ bgin,
                                               float* __restrict__ out) {
    extern __shared__ float sm[];
    float* Wp   = sm;                        // 192*64 floats (48 KB), pair-interleaved
    float* Xs   = Wp + D_SUM * 64;           // 8*8*192 floats (48 KB)
    float* bias = Xs + 8 * 8 * D_SUM;        // 64 floats
    const int tid = threadIdx.x;
    const int colHalf = blockIdx.x & 1;      // which 64-column half
    const int colBase = colHalf * 64;

    for (int i = tid; i < D_SUM * 64; i += 256) {
        int k = i >> 6, j = i & 63;
        int gj = colBase + j;
        float v = (k < D_IN) ? Wgn[k * D_NODE + gj]
                             : Wgin[(k - D_IN) * D_NODE + gj];
        Wp[(k >> 1) * 128 + j * 2 + (k & 1)] = v;
    }
    if (tid < 64) bias[tid] = bgn[colBase + tid] + bgin[colBase + tid];
    __syncthreads();

    const int warp = tid >> 5, lane = tid & 31;
    float* xrow0 = Xs + warp * 8 * D_SUM;
    const float bj0 = bias[lane];
    const float bj1 = bias[lane + 32];
    const int nTiles = (N_NODES + 63) >> 6;  // 64-row tiles
    const int tileStride = gridDim.x >> 1;

    for (int tile = blockIdx.x >> 1; tile < nTiles; tile += tileStride) {
        const int rowBase = tile * 64 + warp * 8;
        #pragma unroll
        for (int i = 0; i < 8; i++) {
            int r = rowBase + i;
            float* xr = xrow0 + i * D_SUM;
            if (r < N_NODES) {
                ((float4*)xr)[lane] = __ldg((const float4*)(X + (size_t)r * D_IN) + lane);
                if (lane < 16)
                    ((float4*)(xr + D_IN))[lane] =
                        *((const float4*)(g_agg + (size_t)r * D_EDGE) + lane);
            } else {
                ((float4*)xr)[lane] = make_float4(0.f, 0.f, 0.f, 0.f);
                if (lane < 16)
                    ((float4*)(xr + D_IN))[lane] = make_float4(0.f, 0.f, 0.f, 0.f);
            }
        }
        __syncwarp();

        ull acc[8][2];
        #pragma unroll
        for (int i = 0; i < 8; i++) { acc[i][0] = 0ull; acc[i][1] = 0ull; }

        for (int kk = 0; kk < D_SUM; kk += 4) {
            const float* wb = Wp + (kk >> 1) * 128;
            ull w0a = *(const ull*)(wb + lane * 2);
            ull w1a = *(const ull*)(wb + (lane + 32) * 2);
            ull w0b = *(const ull*)(wb + 128 + lane * 2);
            ull w1b = *(const ull*)(wb + 128 + (lane + 32) * 2);
            #pragma unroll
            for (int i = 0; i < 8; i++) {
                float4 xv = *(const float4*)(xrow0 + i * D_SUM + kk);
                ull xa = pack2(xv.x, xv.y);
                ull xb = pack2(xv.z, xv.w);
                acc[i][0] = fma2(xa, w0a, acc[i][0]);
                acc[i][1] = fma2(xa, w1a, acc[i][1]);
                acc[i][0] = fma2(xb, w0b, acc[i][0]);
                acc[i][1] = fma2(xb, w1b, acc[i][1]);
            }
        }

        #pragma unroll
        for (int i = 0; i < 8; i++) {
            int r = rowBase + i;
            if (r < N_NODES) {
                float l0, h0, l1, h1;
                unpack2(acc[i][0], l0, h0);
                unpack2(acc[i][1], l1, h1);
                out[(size_t)r * D_NODE + colBase + lane]      = l0 + h0 + bj0;
                out[(size_t)r * D_NODE + colBase + lane + 32] = l1 + h1 + bj1;
            }
        }
        __syncwarp();
    }
}

// ---------------------------------------------------------------------------
extern "C" void kernel_launch(void* const* d_in, const int* in_sizes, int n_in,
                              void* d_out, int out_size) {
    const float* X       = (const float*)d_in[0];
    const float* W_fs    = (const float*)d_in[1];
    const float* b_fs    = (const float*)d_in[2];
    const float* W_gn    = (const float*)d_in[3];
    const float* b_gn    = (const float*)d_in[4];
    const float* W_gin   = (const float*)d_in[5];
    const float* b_gin   = (const float*)d_in[6];
    const int* senders   = (const int*)d_in[7];
    const int* receivers = (const int*)d_in[8];
    float* out = (float*)d_out;

    const int SMEM_A = (D_IN * D_EDGE + 8 * 4 * D_IN) * 4;                 // 48 KB
    const int SMEM_C = (D_SUM * 64 + 8 * 8 * D_SUM + 64) * 4;              // ~96.25 KB

    cudaFuncSetAttribute(k_proj,  cudaFuncAttributeMaxDynamicSharedMemorySize, SMEM_A);
    cudaFuncSetAttribute(k_final, cudaFuncAttributeMaxDynamicSharedMemorySize, SMEM_C);

    k_zero<<<(N_NODES * D_EDGE / 4 + 255) / 256, 256>>>();
    k_proj<<<592, 256, SMEM_A>>>(X, W_fs, b_fs);
    k_edge<<<(N_EDGES * 16 + 255) / 256, 256>>>(senders, receivers);
    k_final<<<296, 256, SMEM_C>>>(X, W_gn, b_gn, W_gin, b_gin, out);
}

// round 7
// speedup vs baseline: 1.7768x; 1.1761x over previous
#include <cuda_runtime.h>
#include <cstdint>

#define N_NODES 50000
#define N_EDGES 1600000
#define D_IN    128
#define D_EDGE  64
#define D_NODE  128
#define D_SUM   (D_IN + D_EDGE)   // 192
#define NPAD    50176             // 49 * 1024 (scan padding)
#define NSCANB  49

// Scratch (allocation-free rule: __device__ globals)
__device__ float g_proj[(size_t)N_NODES * D_EDGE];  // relu(X@W_fs + b_fs), 12.8 MB
__device__ float g_agg [(size_t)N_NODES * D_EDGE];  // segment_max result,  12.8 MB
__device__ int   g_cnt [NPAD];                      // per-receiver degree
__device__ int   g_off [NPAD];                      // block-local excl offsets -> end offsets
__device__ int   g_part[NSCANB];                    // per-scan-block base
__device__ int   g_sid [N_EDGES];                   // sender ids bucketed by receiver

typedef unsigned long long ull;

__device__ __forceinline__ ull pack2(float lo, float hi) {
    ull r;
    asm("mov.b64 %0, {%1, %2};" : "=l"(r) : "f"(lo), "f"(hi));
    return r;
}
__device__ __forceinline__ void unpack2(ull v, float& lo, float& hi) {
    asm("mov.b64 {%0, %1}, %2;" : "=f"(lo), "=f"(hi) : "l"(v));
}
// Packed fp32x2 FMA (sm_103a FFMA2): 2 fp32 FMAs per instruction.
__device__ __forceinline__ ull fma2(ull a, ull b, ull c) {
    ull d;
    asm("fma.rn.f32x2 %0, %1, %2, %3;" : "=l"(d) : "l"(a), "l"(b), "l"(c));
    return d;
}
__device__ __forceinline__ float4 max4(float4 a, float4 b) {
    return make_float4(fmaxf(a.x, b.x), fmaxf(a.y, b.y),
                       fmaxf(a.z, b.z), fmaxf(a.w, b.w));
}

// ---------------------------------------------------------------------------
// Zero the degree histogram (must be re-zeroed every launch; atomics below).
// ---------------------------------------------------------------------------
__global__ void k_zero_cnt() {
    int i = blockIdx.x * 256 + threadIdx.x;
    if (i < NPAD / 4) ((int4*)g_cnt)[i] = make_int4(0, 0, 0, 0);
}

// ---------------------------------------------------------------------------
// Histogram receivers. int4-vectorized (N_EDGES % 4 == 0).
// ---------------------------------------------------------------------------
__global__ __launch_bounds__(256) void k_hist(const int* __restrict__ receivers) {
    int e4 = blockIdx.x * 256 + threadIdx.x;
    if (e4 >= N_EDGES / 4) return;
    int4 r = __ldg((const int4*)receivers + e4);
    atomicAdd(&g_cnt[r.x], 1);
    atomicAdd(&g_cnt[r.y], 1);
    atomicAdd(&g_cnt[r.z], 1);
    atomicAdd(&g_cnt[r.w], 1);
}

// ---------------------------------------------------------------------------
// Scan stage 1: per-1024-block exclusive scan of g_cnt -> g_off, totals -> g_part.
// ---------------------------------------------------------------------------
__global__ __launch_bounds__(1024) void k_scan1() {
    __shared__ int wsum[32];
    int t = threadIdx.x;
    int i = blockIdx.x * 1024 + t;
    int v = g_cnt[i];
    int x = v;
    #pragma unroll
    for (int d = 1; d < 32; d <<= 1) {
        int y = __shfl_up_sync(0xffffffffu, x, d);
        if ((t & 31) >= d) x += y;
    }
    if ((t & 31) == 31) wsum[t >> 5] = x;
    __syncthreads();
    if (t < 32) {
        int y = wsum[t];
        #pragma unroll
        for (int d = 1; d < 32; d <<= 1) {
            int z = __shfl_up_sync(0xffffffffu, y, d);
            if (t >= d) y += z;
        }
        wsum[t] = y;
    }
    __syncthreads();
    int base = (t >= 32) ? wsum[(t >> 5) - 1] : 0;
    g_off[i] = base + x - v;             // block-local exclusive prefix
    if (t == 1023) g_part[blockIdx.x] = wsum[31];  // block total
}

// ---------------------------------------------------------------------------
// Scan stage 2: exclusive scan of the 49 block totals (single block, 64 thr).
// ---------------------------------------------------------------------------
__global__ void k_scan2() {
    __shared__ int w0tot;
    int t = threadIdx.x;
    int v = (t < NSCANB) ? g_part[t] : 0;
    int x = v;
    #pragma unroll
    for (int d = 1; d < 32; d <<= 1) {
        int y = __shfl_up_sync(0xffffffffu, x, d);
        if ((t & 31) >= d) x += y;
    }
    if (t == 31) w0tot = x;
    __syncthreads();
    if (t >= 32) x += w0tot;
    if (t < NSCANB) g_part[t] = x - v;   // exclusive base per scan block
}

// ---------------------------------------------------------------------------
// Scatter: bucket sender ids by receiver. Uses g_off as a per-receiver cursor
// (local-excl); global slot = cursor + g_part[r>>10]. After this kernel,
// g_off[r] = local inclusive prefix (segment end - g_part base).
// ---------------------------------------------------------------------------
__global__ __launch_bounds__(256) void k_scatter(const int* __restrict__ senders,
                                                 const int* __restrict__ receivers) {
    int e4 = blockIdx.x * 256 + threadIdx.x;
    if (e4 >= N_EDGES / 4) return;
    int4 r = __ldg((const int4*)receivers + e4);
    int4 s = __ldg((const int4*)senders + e4);
    int p;
    p = atomicAdd(&g_off[r.x], 1) + g_part[r.x >> 10]; g_sid[p] = s.x;
    p = atomicAdd(&g_off[r.y], 1) + g_part[r.y >> 10]; g_sid[p] = s.y;
    p = atomicAdd(&g_off[r.z], 1) + g_part[r.z >> 10]; g_sid[p] = s.z;
    p = atomicAdd(&g_off[r.w], 1) + g_part[r.w >> 10]; g_sid[p] = s.w;
}

// ---------------------------------------------------------------------------
// Kernel A: g_proj = relu(X @ W_fs + b_fs)   [50000,128]@[128,64]
// ---------------------------------------------------------------------------
__global__ __launch_bounds__(256) void k_proj(const float* __restrict__ X,
                                              const float* __restrict__ W,
                                              const float* __restrict__ b) {
    extern __shared__ float sm[];
    float* Wp = sm;                         // 128*64 floats (32 KB)
    float* Xs = sm + D_IN * D_EDGE;         // 8*4*128 floats (16 KB)
    const int tid = threadIdx.x;

    for (int i = tid; i < D_IN * D_EDGE; i += 256) {
        int k = i >> 6, j = i & 63;
        Wp[(k >> 1) * 128 + j * 2 + (k & 1)] = W[i];
    }
    __syncthreads();

    const int warp = tid >> 5, lane = tid & 31;
    float* xrow0 = Xs + warp * 4 * D_IN;
    const float bj0 = __ldg(&b[lane]);
    const float bj1 = __ldg(&b[lane + 32]);
    const int nTiles = (N_NODES + 31) >> 5;

    for (int tile = blockIdx.x; tile < nTiles; tile += gridDim.x) {
        const int rowBase = tile * 32 + warp * 4;
        #pragma unroll
        for (int i = 0; i < 4; i++) {
            int r = rowBase + i;
            float4 v = make_float4(0.f, 0.f, 0.f, 0.f);
            if (r < N_NODES)
                v = __ldg((const float4*)(X + (size_t)r * D_IN) + lane);
            ((float4*)(xrow0 + i * D_IN))[lane] = v;
        }
        __syncwarp();

        ull acc[4][2];
        #pragma unroll
        for (int i = 0; i < 4; i++) { acc[i][0] = 0ull; acc[i][1] = 0ull; }

        for (int kk = 0; kk < D_IN; kk += 4) {
            const float* wb = Wp + (kk >> 1) * 128;
            ull w0a = *(const ull*)(wb + lane * 2);
            ull w1a = *(const ull*)(wb + (lane + 32) * 2);
            ull w0b = *(const ull*)(wb + 128 + lane * 2);
            ull w1b = *(const ull*)(wb + 128 + (lane + 32) * 2);
            #pragma unroll
            for (int i = 0; i < 4; i++) {
                float4 xv = *(const float4*)(xrow0 + i * D_IN + kk);
                ull xa = pack2(xv.x, xv.y);
                ull xb = pack2(xv.z, xv.w);
                acc[i][0] = fma2(xa, w0a, acc[i][0]);
                acc[i][1] = fma2(xa, w1a, acc[i][1]);
                acc[i][0] = fma2(xb, w0b, acc[i][0]);
                acc[i][1] = fma2(xb, w1b, acc[i][1]);
            }
        }

        #pragma unroll
        for (int i = 0; i < 4; i++) {
            int r = rowBase + i;
            if (r < N_NODES) {
                float l0, h0, l1, h1;
                unpack2(acc[i][0], l0, h0);
                unpack2(acc[i][1], l1, h1);
                g_proj[(size_t)r * D_EDGE + lane]      = fmaxf(l0 + h0 + bj0, 0.f);
                g_proj[(size_t)r * D_EDGE + lane + 32] = fmaxf(l1 + h1 + bj1, 0.f);
            }
        }
        __syncwarp();
    }
}

// ---------------------------------------------------------------------------
// Segment max, atomic-free: half-warp (16 lanes) per node, lane q owns float4
// column q. 4-wide unroll: batch 4 independent sid loads, then 4 row loads,
// doubling per-thread MLP on the dependent LDG->LDG chain. Max is order-
// invariant; remainder loop handles deg % 4. Empty segments write 0.
// ---------------------------------------------------------------------------
__global__ __launch_bounds__(256) void k_gmax() {
    int gid = blockIdx.x * 256 + threadIdx.x;
    int node = gid >> 4;
    if (node >= N_NODES) return;
    int q = gid & 15;
    int end   = g_off[node] + g_part[node >> 10];
    int start = (node == 0) ? 0 : (g_off[node - 1] + g_part[(node - 1) >> 10]);
    float4 m = make_float4(0.f, 0.f, 0.f, 0.f);
    int j = start;
    for (; j + 3 < end; j += 4) {
        int s0 = __ldg(&g_sid[j]);
        int s1 = __ldg(&g_sid[j + 1]);
        int s2 = __ldg(&g_sid[j + 2]);
        int s3 = __ldg(&g_sid[j + 3]);
        float4 v0 = __ldg((const float4*)g_proj + s0 * 16 + q);
        float4 v1 = __ldg((const float4*)g_proj + s1 * 16 + q);
        float4 v2 = __ldg((const float4*)g_proj + s2 * 16 + q);
        float4 v3 = __ldg((const float4*)g_proj + s3 * 16 + q);
        m = max4(m, max4(max4(v0, v1), max4(v2, v3)));
    }
    for (; j < end; j++) {
        int s0 = __ldg(&g_sid[j]);
        float4 v0 = __ldg((const float4*)g_proj + s0 * 16 + q);
        m = max4(m, v0);
    }
    ((float4*)g_agg)[node * 16 + q] = m;
}

// ---------------------------------------------------------------------------
// Kernel C: out = X@W_gn + agg@W_gin + (b_gn + b_gin)
// Fused [X | agg] (192) @ [W_gn ; W_gin] (192x128), column-split (64 cols/block).
// 4 rows/warp, 32-row tiles: smem 72.25KB -> 3 blocks/SM, 24 resident warps.
// ---------------------------------------------------------------------------
__global__ __launch_bounds__(256, 3) void k_final(const float* __restrict__ X,
                                                  const float* __restrict__ Wgn,
                                                  const float* __restrict__ bgn,
                                                  const float* __restrict__ Wgin,
                                                  const float* __restrict__ bgin,
                                                  float* __restrict__ out) {
    extern __shared__ float sm[];
    float* Wp   = sm;                        // 192*64 floats (48 KB), pair-interleaved
    float* Xs   = Wp + D_SUM * 64;           // 8*4*192 floats (24 KB)
    float* bias = Xs + 8 * 4 * D_SUM;        // 64 floats
    const int tid = threadIdx.x;
    const int colBase = (blockIdx.x & 1) * 64;

    for (int i = tid; i < D_SUM * 64; i += 256) {
        int k = i >> 6, j = i & 63;
        int gj = colBase + j;
        float v = (k < D_IN) ? Wgn[k * D_NODE + gj]
                             : Wgin[(k - D_IN) * D_NODE + gj];
        Wp[(k >> 1) * 128 + j * 2 + (k & 1)] = v;
    }
    if (tid < 64) bias[tid] = bgn[colBase + tid] + bgin[colBase + tid];
    __syncthreads();

    const int warp = tid >> 5, lane = tid & 31;
    float* xrow0 = Xs + warp * 4 * D_SUM;
    const float bj0 = bias[lane];
    const float bj1 = bias[lane + 32];
    const int nTiles = (N_NODES + 31) >> 5;   // 32-row tiles
    const int tileStride = gridDim.x >> 1;

    for (int tile = blockIdx.x >> 1; tile < nTiles; tile += tileStride) {
        const int rowBase = tile * 32 + warp * 4;
        #pragma unroll
        for (int i = 0; i < 4; i++) {
            int r = rowBase + i;
            float* xr = xrow0 + i * D_SUM;
            if (r < N_NODES) {
                ((float4*)xr)[lane] = __ldg((const float4*)(X + (size_t)r * D_IN) + lane);
                if (lane < 16)
                    ((float4*)(xr + D_IN))[lane] =
                        *((const float4*)(g_agg + (size_t)r * D_EDGE) + lane);
            } else {
                ((float4*)xr)[lane] = make_float4(0.f, 0.f, 0.f, 0.f);
                if (lane < 16)
                    ((float4*)(xr + D_IN))[lane] = make_float4(0.f, 0.f, 0.f, 0.f);
            }
        }
        __syncwarp();

        ull acc[4][2];
        #pragma unroll
        for (int i = 0; i < 4; i++) { acc[i][0] = 0ull; acc[i][1] = 0ull; }

        for (int kk = 0; kk < D_SUM; kk += 4) {
            const float* wb = Wp + (kk >> 1) * 128;
            ull w0a = *(const ull*)(wb + lane * 2);
            ull w1a = *(const ull*)(wb + (lane + 32) * 2);
            ull w0b = *(const ull*)(wb + 128 + lane * 2);
            ull w1b = *(const ull*)(wb + 128 + (lane + 32) * 2);
            #pragma unroll
            for (int i = 0; i < 4; i++) {
                float4 xv = *(const float4*)(xrow0 + i * D_SUM + kk);
                ull xa = pack2(xv.x, xv.y);
                ull xb = pack2(xv.z, xv.w);
                acc[i][0] = fma2(xa, w0a, acc[i][0]);
                acc[i][1] = fma2(xa, w1a, acc[i][1]);
                acc[i][0] = fma2(xb, w0b, acc[i][0]);
                acc[i][1] = fma2(xb, w1b, acc[i][1]);
            }
        }

        #pragma unroll
        for (int i = 0; i < 4; i++) {
            int r = rowBase + i;
            if (r < N_NODES) {
                float l0, h0, l1, h1;
                unpack2(acc[i][0], l0, h0);
                unpack2(acc[i][1], l1, h1);
                out[(size_t)r * D_NODE + colBase + lane]      = l0 + h0 + bj0;
                out[(size_t)r * D_NODE + colBase + lane + 32] = l1 + h1 + bj1;
            }
        }
        __syncwarp();
    }
}

// ---------------------------------------------------------------------------
extern "C" void kernel_launch(void* const* d_in, const int* in_sizes, int n_in,
                              void* d_out, int out_size) {
    const float* X       = (const float*)d_in[0];
    const float* W_fs    = (const float*)d_in[1];
    const float* b_fs    = (const float*)d_in[2];
    const float* W_gn    = (const float*)d_in[3];
    const float* b_gn    = (const float*)d_in[4];
    const float* W_gin   = (const float*)d_in[5];
    const float* b_gin   = (const float*)d_in[6];
    const int* senders   = (const int*)d_in[7];
    const int* receivers = (const int*)d_in[8];
    float* out = (float*)d_out;

    const int SMEM_A = (D_IN * D_EDGE + 8 * 4 * D_IN) * 4;          // 48 KB
    const int SMEM_C = (D_SUM * 64 + 8 * 4 * D_SUM + 64) * 4;       // ~72.25 KB

    cudaFuncSetAttribute(k_proj,  cudaFuncAttributeMaxDynamicSharedMemorySize, SMEM_A);
    cudaFuncSetAttribute(k_final, cudaFuncAttributeMaxDynamicSharedMemorySize, SMEM_C);

    k_zero_cnt<<<(NPAD / 4 + 255) / 256, 256>>>();
    k_hist<<<(N_EDGES / 4 + 255) / 256, 256>>>(receivers);
    k_scan1<<<NSCANB, 1024>>>();
    k_scan2<<<1, 64>>>();
    k_scatter<<<(N_EDGES / 4 + 255) / 256, 256>>>(senders, receivers);
    k_proj<<<592, 256, SMEM_A>>>(X, W_fs, b_fs);
    k_gmax<<<(N_NODES * 16 + 255) / 256, 256>>>();
    k_final<<<444, 256, SMEM_C>>>(X, W_gn, b_gn, W_gin, b_gin, out);
}

// round 9
// speedup vs baseline: 1.8160x; 1.0221x over previous
#include <cuda_runtime.h>
#include <cstdint>

#define N_NODES 50000
#define N_EDGES 1600000
#define D_IN    128
#define D_EDGE  64
#define D_NODE  128
#define D_SUM   (D_IN + D_EDGE)   // 192
#define NPAD    50176             // 49 * 1024 (scan padding)
#define NSCANB  49

// Scratch (allocation-free rule: __device__ globals)
__device__ float g_proj[(size_t)N_NODES * D_EDGE];  // relu(X@W_fs + b_fs), 12.8 MB
__device__ float g_agg [(size_t)N_NODES * D_EDGE];  // segment_max result,  12.8 MB
__device__ int   g_cnt [NPAD];                      // per-receiver degree
__device__ int   g_off [NPAD];                      // block-local excl offsets -> end offsets
__device__ int   g_part[NSCANB];                    // per-scan-block base
__device__ int   g_sid [N_EDGES];                   // sender ids bucketed by receiver

typedef unsigned long long ull;

__device__ __forceinline__ ull pack2(float lo, float hi) {
    ull r;
    asm("mov.b64 %0, {%1, %2};" : "=l"(r) : "f"(lo), "f"(hi));
    return r;
}
__device__ __forceinline__ void unpack2(ull v, float& lo, float& hi) {
    asm("mov.b64 {%0, %1}, %2;" : "=f"(lo), "=f"(hi) : "l"(v));
}
// Packed fp32x2 FMA (sm_103a FFMA2): 2 fp32 FMAs per instruction.
__device__ __forceinline__ ull fma2(ull a, ull b, ull c) {
    ull d;
    asm("fma.rn.f32x2 %0, %1, %2, %3;" : "=l"(d) : "l"(a), "l"(b), "l"(c));
    return d;
}
__device__ __forceinline__ float4 max4(float4 a, float4 b) {
    return make_float4(fmaxf(a.x, b.x), fmaxf(a.y, b.y),
                       fmaxf(a.z, b.z), fmaxf(a.w, b.w));
}

// ---------------------------------------------------------------------------
// Zero the degree histogram (must be re-zeroed every launch; atomics below).
// ---------------------------------------------------------------------------
__global__ void k_zero_cnt() {
    int i = blockIdx.x * 256 + threadIdx.x;
    if (i < NPAD / 4) ((int4*)g_cnt)[i] = make_int4(0, 0, 0, 0);
}

// ---------------------------------------------------------------------------
// Histogram receivers. int4-vectorized (N_EDGES % 4 == 0).
// ---------------------------------------------------------------------------
__global__ __launch_bounds__(256) void k_hist(const int* __restrict__ receivers) {
    int e4 = blockIdx.x * 256 + threadIdx.x;
    if (e4 >= N_EDGES / 4) return;
    int4 r = __ldg((const int4*)receivers + e4);
    atomicAdd(&g_cnt[r.x], 1);
    atomicAdd(&g_cnt[r.y], 1);
    atomicAdd(&g_cnt[r.z], 1);
    atomicAdd(&g_cnt[r.w], 1);
}

// ---------------------------------------------------------------------------
// Scan stage 1: per-1024-block exclusive scan of g_cnt -> g_off, totals -> g_part.
// ---------------------------------------------------------------------------
__global__ __launch_bounds__(1024) void k_scan1() {
    __shared__ int wsum[32];
    int t = threadIdx.x;
    int i = blockIdx.x * 1024 + t;
    int v = g_cnt[i];
    int x = v;
    #pragma unroll
    for (int d = 1; d < 32; d <<= 1) {
        int y = __shfl_up_sync(0xffffffffu, x, d);
        if ((t & 31) >= d) x += y;
    }
    if ((t & 31) == 31) wsum[t >> 5] = x;
    __syncthreads();
    if (t < 32) {
        int y = wsum[t];
        #pragma unroll
        for (int d = 1; d < 32; d <<= 1) {
            int z = __shfl_up_sync(0xffffffffu, y, d);
            if (t >= d) y += z;
        }
        wsum[t] = y;
    }
    __syncthreads();
    int base = (t >= 32) ? wsum[(t >> 5) - 1] : 0;
    g_off[i] = base + x - v;             // block-local exclusive prefix
    if (t == 1023) g_part[blockIdx.x] = wsum[31];  // block total
}

// ---------------------------------------------------------------------------
// Scan stage 2: exclusive scan of the 49 block totals (single block, 64 thr).
// ---------------------------------------------------------------------------
__global__ void k_scan2() {
    __shared__ int w0tot;
    int t = threadIdx.x;
    int v = (t < NSCANB) ? g_part[t] : 0;
    int x = v;
    #pragma unroll
    for (int d = 1; d < 32; d <<= 1) {
        int y = __shfl_up_sync(0xffffffffu, x, d);
        if ((t & 31) >= d) x += y;
    }
    if (t == 31) w0tot = x;
    __syncthreads();
    if (t >= 32) x += w0tot;
    if (t < NSCANB) g_part[t] = x - v;   // exclusive base per scan block
}

// ---------------------------------------------------------------------------
// Scatter: bucket sender ids by receiver. Uses g_off as a per-receiver cursor
// (local-excl); global slot = cursor + g_part[r>>10]. After this kernel,
// g_off[r] = local inclusive prefix (segment end - g_part base).
// ---------------------------------------------------------------------------
__global__ __launch_bounds__(256) void k_scatter(const int* __restrict__ senders,
                                                 const int* __restrict__ receivers) {
    int e4 = blockIdx.x * 256 + threadIdx.x;
    if (e4 >= N_EDGES / 4) return;
    int4 r = __ldg((const int4*)receivers + e4);
    int4 s = __ldg((const int4*)senders + e4);
    int p;
    p = atomicAdd(&g_off[r.x], 1) + g_part[r.x >> 10]; g_sid[p] = s.x;
    p = atomicAdd(&g_off[r.y], 1) + g_part[r.y >> 10]; g_sid[p] = s.y;
    p = atomicAdd(&g_off[r.z], 1) + g_part[r.z >> 10]; g_sid[p] = s.z;
    p = atomicAdd(&g_off[r.w], 1) + g_part[r.w >> 10]; g_sid[p] = s.w;
}

// ---------------------------------------------------------------------------
// Kernel A: g_proj = relu(X @ W_fs + b_fs)   [50000,128]@[128,64]
// Runs on a forked stream, overlapped with the CSR prep chain.
// ---------------------------------------------------------------------------
__global__ __launch_bounds__(256) void k_proj(const float* __restrict__ X,
                                              const float* __restrict__ W,
                                              const float* __restrict__ b) {
    extern __shared__ float sm[];
    float* Wp = sm;                         // 128*64 floats (32 KB)
    float* Xs = sm + D_IN * D_EDGE;         // 8*4*128 floats (16 KB)
    const int tid = threadIdx.x;

    for (int i = tid; i < D_IN * D_EDGE; i += 256) {
        int k = i >> 6, j = i & 63;
        Wp[(k >> 1) * 128 + j * 2 + (k & 1)] = W[i];
    }
    __syncthreads();

    const int warp = tid >> 5, lane = tid & 31;
    float* xrow0 = Xs + warp * 4 * D_IN;
    const float bj0 = __ldg(&b[lane]);
    const float bj1 = __ldg(&b[lane + 32]);
    const int nTiles = (N_NODES + 31) >> 5;

    for (int tile = blockIdx.x; tile < nTiles; tile += gridDim.x) {
        const int rowBase = tile * 32 + warp * 4;
        #pragma unroll
        for (int i = 0; i < 4; i++) {
            int r = rowBase + i;
            float4 v = make_float4(0.f, 0.f, 0.f, 0.f);
            if (r < N_NODES)
                v = __ldg((const float4*)(X + (size_t)r * D_IN) + lane);
            ((float4*)(xrow0 + i * D_IN))[lane] = v;
        }
        __syncwarp();

        ull acc[4][2];
        #pragma unroll
        for (int i = 0; i < 4; i++) { acc[i][0] = 0ull; acc[i][1] = 0ull; }

        for (int kk = 0; kk < D_IN; kk += 4) {
            const float* wb = Wp + (kk >> 1) * 128;
            ull w0a = *(const ull*)(wb + lane * 2);
            ull w1a = *(const ull*)(wb + (lane + 32) * 2);
            ull w0b = *(const ull*)(wb + 128 + lane * 2);
            ull w1b = *(const ull*)(wb + 128 + (lane + 32) * 2);
            #pragma unroll
            for (int i = 0; i < 4; i++) {
                float4 xv = *(const float4*)(xrow0 + i * D_IN + kk);
                ull xa = pack2(xv.x, xv.y);
                ull xb = pack2(xv.z, xv.w);
                acc[i][0] = fma2(xa, w0a, acc[i][0]);
                acc[i][1] = fma2(xa, w1a, acc[i][1]);
                acc[i][0] = fma2(xb, w0b, acc[i][0]);
                acc[i][1] = fma2(xb, w1b, acc[i][1]);
            }
        }

        #pragma unroll
        for (int i = 0; i < 4; i++) {
            int r = rowBase + i;
            if (r < N_NODES) {
                float l0, h0, l1, h1;
                unpack2(acc[i][0], l0, h0);
                unpack2(acc[i][1], l1, h1);
                g_proj[(size_t)r * D_EDGE + lane]      = fmaxf(l0 + h0 + bj0, 0.f);
                g_proj[(size_t)r * D_EDGE + lane + 32] = fmaxf(l1 + h1 + bj1, 0.f);
            }
        }
        __syncwarp();
    }
}

// ---------------------------------------------------------------------------
// Segment max, atomic-free: half-warp (16 lanes) per node, lane q owns float4
// column q. 4-wide unroll batches independent loads on the LDG->LDG chain.
// ---------------------------------------------------------------------------
__global__ __launch_bounds__(256) void k_gmax() {
    int gid = blockIdx.x * 256 + threadIdx.x;
    int node = gid >> 4;
    if (node >= N_NODES) return;
    int q = gid & 15;
    int end   = g_off[node] + g_part[node >> 10];
    int start = (node == 0) ? 0 : (g_off[node - 1] + g_part[(node - 1) >> 10]);
    float4 m = make_float4(0.f, 0.f, 0.f, 0.f);
    int j = start;
    for (; j + 3 < end; j += 4) {
        int s0 = __ldg(&g_sid[j]);
        int s1 = __ldg(&g_sid[j + 1]);
        int s2 = __ldg(&g_sid[j + 2]);
        int s3 = __ldg(&g_sid[j + 3]);
        float4 v0 = __ldg((const float4*)g_proj + s0 * 16 + q);
        float4 v1 = __ldg((const float4*)g_proj + s1 * 16 + q);
        float4 v2 = __ldg((const float4*)g_proj + s2 * 16 + q);
        float4 v3 = __ldg((const float4*)g_proj + s3 * 16 + q);
        m = max4(m, max4(max4(v0, v1), max4(v2, v3)));
    }
    for (; j < end; j++) {
        int s0 = __ldg(&g_sid[j]);
        float4 v0 = __ldg((const float4*)g_proj + s0 * 16 + q);
        m = max4(m, v0);
    }
    ((float4*)g_agg)[node * 16 + q] = m;
}

// ---------------------------------------------------------------------------
// Kernel C: out = X@W_gn + agg@W_gin + (b_gn + b_gin)
// Fused [X | agg] (192) @ [W_gn ; W_gin] (192x128), column-split (64 cols/block).
// 4 rows/warp, 32-row tiles: smem 72.25KB -> 3 blocks/SM, 24 resident warps.
// ---------------------------------------------------------------------------
__global__ __launch_bounds__(256, 3) void k_final(const float* __restrict__ X,
                                                  const float* __restrict__ Wgn,
                                                  const float* __restrict__ bgn,
                                                  const float* __restrict__ Wgin,
                                                  const float* __restrict__ bgin,
                                                  float* __restrict__ out) {
    extern __shared__ float sm[];
    float* Wp   = sm;                        // 192*64 floats (48 KB), pair-interleaved
    float* Xs   = Wp + D_SUM * 64;           // 8*4*192 floats (24 KB)
    float* bias = Xs + 8 * 4 * D_SUM;        // 64 floats
    const int tid = threadIdx.x;
    const int colBase = (blockIdx.x & 1) * 64;

    for (int i = tid; i < D_SUM * 64; i += 256) {
        int k = i >> 6, j = i & 63;
        int gj = colBase + j;
        float v = (k < D_IN) ? Wgn[k * D_NODE + gj]
                             : Wgin[(k - D_IN) * D_NODE + gj];
        Wp[(k >> 1) * 128 + j * 2 + (k & 1)] = v;
    }
    if (tid < 64) bias[tid] = bgn[colBase + tid] + bgin[colBase + tid];
    __syncthreads();

    const int warp = tid >> 5, lane = tid & 31;
    float* xrow0 = Xs + warp * 4 * D_SUM;
    const float bj0 = bias[lane];
    const float bj1 = bias[lane + 32];
    const int nTiles = (N_NODES + 31) >> 5;   // 32-row tiles
    const int tileStride = gridDim.x >> 1;

    for (int tile = blockIdx.x >> 1; tile < nTiles; tile += tileStride) {
        const int rowBase = tile * 32 + warp * 4;
        #pragma unroll
        for (int i = 0; i < 4; i++) {
            int r = rowBase + i;
            float* xr = xrow0 + i * D_SUM;
            if (r < N_NODES) {
                ((float4*)xr)[lane] = __ldg((const float4*)(X + (size_t)r * D_IN) + lane);
                if (lane < 16)
                    ((float4*)(xr + D_IN))[lane] =
                        *((const float4*)(g_agg + (size_t)r * D_EDGE) + lane);
            } else {
                ((float4*)xr)[lane] = make_float4(0.f, 0.f, 0.f, 0.f);
                if (lane < 16)
                    ((float4*)(xr + D_IN))[lane] = make_float4(0.f, 0.f, 0.f, 0.f);
            }
        }
        __syncwarp();

        ull acc[4][2];
        #pragma unroll
        for (int i = 0; i < 4; i++) { acc[i][0] = 0ull; acc[i][1] = 0ull; }

        for (int kk = 0; kk < D_SUM; kk += 4) {
            const float* wb = Wp + (kk >> 1) * 128;
            ull w0a = *(const ull*)(wb + lane * 2);
            ull w1a = *(const ull*)(wb + (lane + 32) * 2);
            ull w0b = *(const ull*)(wb + 128 + lane * 2);
            ull w1b = *(const ull*)(wb + 128 + (lane + 32) * 2);
            #pragma unroll
            for (int i = 0; i < 4; i++) {
                float4 xv = *(const float4*)(xrow0 + i * D_SUM + kk);
                ull xa = pack2(xv.x, xv.y);
                ull xb = pack2(xv.z, xv.w);
                acc[i][0] = fma2(xa, w0a, acc[i][0]);
                acc[i][1] = fma2(xa, w1a, acc[i][1]);
                acc[i][0] = fma2(xb, w0b, acc[i][0]);
                acc[i][1] = fma2(xb, w1b, acc[i][1]);
            }
        }

        #pragma unroll
        for (int i = 0; i < 4; i++) {
            int r = rowBase + i;
            if (r < N_NODES) {
                float l0, h0, l1, h1;
                unpack2(acc[i][0], l0, h0);
                unpack2(acc[i][1], l1, h1);
                out[(size_t)r * D_NODE + colBase + lane]      = l0 + h0 + bj0;
                out[(size_t)r * D_NODE + colBase + lane + 32] = l1 + h1 + bj1;
            }
        }
        __syncwarp();
    }
}

// ---------------------------------------------------------------------------
extern "C" void kernel_launch(void* const* d_in, const int* in_sizes, int n_in,
                              void* d_out, int out_size) {
    const float* X       = (const float*)d_in[0];
    const float* W_fs    = (const float*)d_in[1];
    const float* b_fs    = (const float*)d_in[2];
    const float* W_gn    = (const float*)d_in[3];
    const float* b_gn    = (const float*)d_in[4];
    const float* W_gin   = (const float*)d_in[5];
    const float* b_gin   = (const float*)d_in[6];
    const int* senders   = (const int*)d_in[7];
    const int* receivers = (const int*)d_in[8];
    float* out = (float*)d_out;

    const int SMEM_A = (D_IN * D_EDGE + 8 * 4 * D_IN) * 4;          // 48 KB
    const int SMEM_C = (D_SUM * 64 + 8 * 4 * D_SUM + 64) * 4;       // ~72.25 KB

    cudaFuncSetAttribute(k_proj,  cudaFuncAttributeMaxDynamicSharedMemorySize, SMEM_A);
    cudaFuncSetAttribute(k_final, cudaFuncAttributeMaxDynamicSharedMemorySize, SMEM_C);

    // Fork a side stream for k_proj (independent of CSR prep).
    // Created per call, never destroyed while capture may be active.
    cudaStream_t sProj;
    cudaStreamCreateWithFlags(&sProj, cudaStreamNonBlocking);
    cudaEvent_t evFork, evProjDone;
    cudaEventCreateWithFlags(&evFork, cudaEventDisableTiming);
    cudaEventCreateWithFlags(&evProjDone, cudaEventDisableTiming);

    cudaEventRecord(evFork, 0);
    cudaStreamWaitEvent(sProj, evFork, 0);
    k_proj<<<592, 256, SMEM_A, sProj>>>(X, W_fs, b_fs);
    cudaEventRecord(evProjDone, sProj);

    // CSR prep chain on the main (capture) stream, overlapped with k_proj.
    k_zero_cnt<<<(NPAD / 4 + 255) / 256, 256>>>();
    k_hist<<<(N_EDGES / 4 + 255) / 256, 256>>>(receivers);
    k_scan1<<<NSCANB, 1024>>>();
    k_scan2<<<1, 64>>>();
    k_scatter<<<(N_EDGES / 4 + 255) / 256, 256>>>(senders, receivers);

    // Join: k_gmax needs both g_proj and the CSR arrays.
    cudaStreamWaitEvent(0, evProjDone, 0);
    k_gmax<<<(N_NODES * 16 + 255) / 256, 256>>>();
    k_final<<<444, 256, SMEM_C>>>(X, W_gn, b_gn, W_gin, b_gin, out);
}